// round 17
// baseline (speedup 1.0000x reference)
#include <cuda_runtime.h>
#include <cuda_fp16.h>
#include <cstdint>
#include <cstddef>

#define BB   8
#define NPTS 4096
#define SS   2048
#define KNB  64
#define CIN  64
#define HID  128
#define BSZ  (BB*SS)
#define R2F  0.04f
#define MAXC 1024
#define NBLK (BSZ/2)          // 2 centroids per GEMM block
#define SROW 132              // fp32 staging row stride
#define NT   256              // threads per block

// ---------------- device scratch ----------------
__device__ float  g_ctr[BSZ*3];
__device__ int    g_cnt[BSZ];
__device__ int    g_prog[BB];
__device__ float4 g_pos4[BB*NPTS];
__device__ uint2  g_H0h[(size_t)NBLK*4096];
__device__ uint2  g_H1h[(size_t)NBLK*4096];
__device__ double g_stat[2][2][32][HID];
__device__ float  g_scale[2][HID];
__device__ float  g_shift[2][HID];
__device__ uint32_t g_WF0[3*4096];
__device__ uint32_t g_WF1[4*4096];
__device__ uint32_t g_WF2[4*4096];

// ---------------- helpers ----------------
__device__ __forceinline__ uint32_t smem_u32(const void* p) {
    uint32_t a;
    asm("{ .reg .u64 t; cvta.to.shared.u64 t, %1; cvt.u32.u64 %0, t; }" : "=r"(a) : "l"(p));
    return a;
}
__device__ __forceinline__ void cp16(void* dst, const void* src) {
    asm volatile("cp.async.ca.shared.global [%0], [%1], 16;"
                 :: "r"(smem_u32(dst)), "l"(src) : "memory");
}
#define CP_COMMIT() asm volatile("cp.async.commit_group;" ::: "memory")
#define CP_WAIT0()  asm volatile("cp.async.wait_group 0;" ::: "memory")

__device__ __forceinline__ uint32_t h2(float x, float y) {
    __half2 v = __floats2half2_rn(x, y);
    return *(uint32_t*)&v;
}

__device__ __forceinline__ void mma16(float* c, uint32_t a0, uint32_t a1, uint32_t a2,
                                      uint32_t a3, uint32_t b0, uint32_t b1) {
    asm volatile("mma.sync.aligned.m16n8k16.row.col.f32.f16.f16.f32 "
        "{%0,%1,%2,%3}, {%4,%5,%6,%7}, {%8,%9}, {%0,%1,%2,%3};\n"
        : "+f"(c[0]), "+f"(c[1]), "+f"(c[2]), "+f"(c[3])
        : "r"(a0), "r"(a1), "r"(a2), "r"(a3), "r"(b0), "r"(b1));
}

// M=128 tile, 8 warps, warp w owns rows 16w..16w+15 (R15-validated per-warp shape)
__device__ __forceinline__ void gemm_slab(const float* sA, const uint32_t* sB,
                                          float (*acc)[4], int w, int lane, int scol,
                                          int nkk) {
    int g = lane >> 2, tig = lane & 3;
#pragma unroll 1
    for (int kk = 0; kk < nkk; kk++) {
        const float* base = sA + (16*w + g)*SROW + scol + kk*16 + 2*tig;
        float2 v00 = *(const float2*)(base);
        float2 v01 = *(const float2*)(base + 8);
        float2 v10 = *(const float2*)(base + 8*SROW);
        float2 v11 = *(const float2*)(base + 8*SROW + 8);
        uint32_t a0 = h2(v00.x, v00.y);
        uint32_t a1 = h2(v10.x, v10.y);
        uint32_t a2 = h2(v01.x, v01.y);
        uint32_t a3 = h2(v11.x, v11.y);
        const uint32_t* bh = sB + kk*1024;
        const uint32_t* bl = sB + 2048 + kk*1024;
#pragma unroll
        for (int tth = 0; tth < 8; tth++) {
            uint4 b = *(const uint4*)&bh[(tth*32 + lane)*4];
            mma16(acc[2*tth],   a0, a1, a2, a3, b.x, b.y);
            mma16(acc[2*tth+1], a0, a1, a2, a3, b.z, b.w);
        }
#pragma unroll
        for (int tth = 0; tth < 8; tth++) {
            uint4 b = *(const uint4*)&bl[(tth*32 + lane)*4];
            mma16(acc[2*tth],   a0, a1, a2, a3, b.x, b.y);
            mma16(acc[2*tth+1], a0, a1, a2, a3, b.z, b.w);
        }
    }
}

// async B slab copy (256 threads, 4x uint4 each)
__device__ __forceinline__ void stageB(uint32_t* buf, const uint32_t* src, int t) {
#pragma unroll
    for (int i = 0; i < 4; i++) {
        int idx = (t + i*NT) * 4;
        cp16(buf + idx, src + idx);
    }
    CP_COMMIT();
}

// acc -> (+bias) -> staging rows (warp w writes rows 16w..16w+15)
__device__ __forceinline__ void epi_to_stage(float* sA, float (*acc)[4], const float* bias,
                                             int w, int lane) {
    int g = lane >> 2, tig = lane & 3;
#pragma unroll
    for (int tt = 0; tt < 16; tt++) {
        int n0 = tt*8 + tig*2;
        float bz0 = bias[n0], bz1 = bias[n0+1];
        float* r0 = sA + (16*w + g)*SROW + n0;
        const float* a = acc[tt];
        *(float2*)r0            = make_float2(a[0]+bz0, a[1]+bz1);
        *(float2*)(r0 + 8*SROW) = make_float2(a[2]+bz0, a[3]+bz1);
    }
}

__device__ __forceinline__ void stage_to_H(uint2* dstH, const float* sA, int t) {
    for (int i = t; i < 4096; i += NT) {
        const float* s = sA + (i >> 5)*SROW + (i & 31)*4;
        __half2 h0 = __floats2half2_rn(s[0], s[1]);
        __half2 h1 = __floats2half2_rn(s[2], s[3]);
        uint2 u;
        u.x = *(uint32_t*)&h0;
        u.y = *(uint32_t*)&h1;
        dstH[i] = u;
    }
}

__device__ __forceinline__ void H_to_stage(float* sA, const uint2* src, int t,
                                           const float* sc, const float* sh) {
    for (int i = t; i < 4096; i += NT) {
        int row = i >> 5, c4 = (i & 31) * 4;
        uint2 u = src[i];
        float2 f0 = __half22float2(*(__half2*)&u.x);
        float2 f1 = __half22float2(*(__half2*)&u.y);
        float4 z;
        z.x = fmaxf(0.f, fmaf(f0.x, sc[c4+0], sh[c4+0]));
        z.y = fmaxf(0.f, fmaf(f0.y, sc[c4+1], sh[c4+1]));
        z.z = fmaxf(0.f, fmaf(f1.x, sc[c4+2], sh[c4+2]));
        z.w = fmaxf(0.f, fmaf(f1.y, sc[c4+3], sh[c4+3]));
        *(float4*)(sA + row*SROW + c4) = z;
    }
}

// ---------------- weight fragment prep ----------------
__device__ __forceinline__ void wprep_item(const float* __restrict__ W, int K,
                                           uint32_t* dst, int i) {
    int s = i >> 11, r = i & 2047;
    int q = r & 3, lane = (r >> 2) & 31, tth = (r >> 7) & 7, kk = (r >> 10) & 1;
    int reg = q & 1, tto = q >> 1;
    int tt = tth*2 + tto;
    int k0 = s*32 + kk*16 + reg*8 + (lane & 3)*2;
    int n  = tt*8 + (lane >> 2);
    float v0 = (k0     < K) ? W[k0*HID + n]     : 0.f;
    float v1 = (k0 + 1 < K) ? W[(k0+1)*HID + n] : 0.f;
    __half2 hh = __floats2half2_rn(v0, v1);
    float l0 = v0 - __half2float(__low2half(hh));
    float l1 = v1 - __half2float(__high2half(hh));
    dst[s*4096 + r]        = *(uint32_t*)&hh;
    dst[s*4096 + 2048 + r] = h2(l0, l1);
}

__global__ void k_pA(const float* __restrict__ pos) {
    int i = blockIdx.x * blockDim.x + threadIdx.x;
    if (i < 32768) {
        g_pos4[i] = make_float4(pos[3*i], pos[3*i+1], pos[3*i+2], 0.f);
    } else if (i < 49152) {
        (&g_stat[0][0][0][0])[i - 32768] = 0.0;
    } else if (i < 49160) {
        g_prog[i - 49152] = 0;
    }
}
__global__ void k_pB(const float* __restrict__ W0, const float* __restrict__ W1) {
    int i = blockIdx.x * blockDim.x + threadIdx.x;
    if (i < 6144) wprep_item(W0, 67, g_WF0, i);
    else if (i < 14336) wprep_item(W1, HID, g_WF1, i - 6144);
}
__global__ void k_pC(const float* __restrict__ W2) {
    int i = blockIdx.x * blockDim.x + threadIdx.x;
    if (i < 8192) wprep_item(W2, HID, g_WF2, i);
}

// ================= fused: fps(8 blocks, 256t) || [nbr+gather+GEMM l0] =================

__device__ void fps_role(float* sm, int b, int t,
                         float* __restrict__ octr, float* __restrict__ obat) {
    float* sx = sm;
    float* sy = sm + NPTS;
    float* sz = sm + 2*NPTS;
    unsigned* svk = (unsigned*)(sm + 3*NPTS);        // [2][8]
    unsigned* svi = (unsigned*)(sm + 3*NPTS + 16);   // [2][8]
    float px[16], py[16], pz[16], md[16];
#pragma unroll
    for (int j = 0; j < 16; j++) {
        int i = t + j*NT;
        float4 P = g_pos4[b*NPTS + i];
        px[j] = P.x; py[j] = P.y; pz[j] = P.z;
        sx[i] = P.x; sy[i] = P.y; sz[i] = P.z;
        md[j] = __int_as_float(0x7f800000);
    }
    int lane = t & 31, w = t >> 5;
    int last = 0;
    __syncthreads();
    for (int s = 0; s < SS; s++) {
        float qx = sx[last], qy = sy[last], qz = sz[last];
        if (t == 0) {
            int o = b*SS + s;
            g_ctr[o*3] = qx; g_ctr[o*3+1] = qy; g_ctr[o*3+2] = qz;
            if (octr) { octr[o*3] = qx; octr[o*3+1] = qy; octr[o*3+2] = qz; }
            if (obat) obat[o] = (float)b;
        }
        float bv = -1.f; int bi = 0;
#pragma unroll
        for (int j = 0; j < 16; j++) {
            float dx = px[j]-qx, dy = py[j]-qy, dz = pz[j]-qz;
            float d = fmaf(dz, dz, fmaf(dy, dy, __fmul_rn(dx, dx)));
            md[j] = fminf(md[j], d);
            if (md[j] > bv) { bv = md[j]; bi = t + j*NT; }   // strict >: lowest idx wins
        }
        unsigned key  = __float_as_uint(bv);
        unsigned vmax = __reduce_max_sync(0xffffffffu, key);
        unsigned cand = (key == vmax) ? (unsigned)bi : 0xffffffffu;
        unsigned imin = __reduce_min_sync(0xffffffffu, cand);
        int buf = s & 1;
        if (lane == 0) { svk[buf*8 + w] = vmax; svi[buf*8 + w] = imin; }
        __syncthreads();
        unsigned k2 = (lane < 8) ? svk[buf*8 + lane] : 0u;
        unsigned i2 = (lane < 8) ? svi[buf*8 + lane] : 0xffffffffu;
        unsigned vm2 = __reduce_max_sync(0xffffffffu, k2);
        unsigned c2  = (k2 == vm2) ? i2 : 0xffffffffu;
        last = (int)__reduce_min_sync(0xffffffffu, c2);
        if (((s & 15) == 15) && t == 0) {
            __threadfence();
            *((volatile int*)&g_prog[b]) = s + 1;
        }
    }
    if (t == 0) {
        __threadfence();
        *((volatile int*)&g_prog[b]) = SS;
    }
}

// inline radius-capped kNN (256 threads)
__device__ void nbr_one(float* scr, int* nlist, int* cnt_out, int cc, int t) {
    float* sd   = scr;
    int*   sid  = (int*)(scr + 1024);
    int*   hist = (int*)(scr + 2048);
    float* td   = scr + 2176;
    int*   tdi  = (int*)(scr + 2432);
    int*   wtot = (int*)(scr + 2688);
    int*   scal = (int*)(scr + 2692);   // sc, so, s_tb, s_m, tc
    int b = cc >> 11;
    if (t == 0) { scal[0] = 0; scal[1] = 0; scal[4] = 0; }
    if (t < 128) hist[t] = 0;
    float cx = __ldcg(&g_ctr[cc*3]);
    float cy = __ldcg(&g_ctr[cc*3+1]);
    float cz = __ldcg(&g_ctr[cc*3+2]);
    __syncthreads();
    for (int i = t; i < NPTS; i += NT) {
        float4 P = g_pos4[b*NPTS + i];
        float dx = P.x-cx, dy = P.y-cy, dz = P.z-cz;
        float d = fmaf(dz, dz, fmaf(dy, dy, __fmul_rn(dx, dx)));
        if (d <= R2F) {
            int k = atomicAdd(&scal[0], 1);
            if (k < MAXC) { sd[k] = d; sid[k] = i; }
        }
    }
    __syncthreads();
    int cnt = min(scal[0], MAXC);
    if (cnt <= KNB) {
        if (t < cnt) nlist[t] = sid[t];
        if (t == 0) { *cnt_out = cnt; g_cnt[cc] = cnt; }
        __syncthreads();
        return;
    }
    const float bsc = 128.0f / R2F;
    for (int i = t; i < cnt; i += NT) {
        int bk = min(127, (int)(sd[i] * bsc));
        atomicAdd(&hist[bk], 1);
    }
    __syncthreads();
    {
        int lane = t & 31, w = t >> 5;
        if (t < 128) {
            int h = hist[t], v = h;
#pragma unroll
            for (int o = 1; o < 32; o <<= 1) {
                int u = __shfl_up_sync(0xffffffffu, v, o);
                if (lane >= o) v += u;
            }
            if (lane == 31) wtot[w] = v;
            hist[t] = v;          // stash inclusive scan
        }
        __syncthreads();
        if (t < 128) {
            int base = 0;
            for (int k2 = 0; k2 < w; k2++) base += wtot[k2];
            int incl = hist[t] + base;
            // recompute h from scan diff is messy; reload via incl-excl using scan:
            // excl = incl - original h. Original h = incl - (excl)... store orig approach:
            // use separate: nothing else wrote hist before stash except scan. Need orig h:
            // orig h = incl - (lane? prev incl in warp...). Simpler: recompute below.
            (void)incl;
        }
        __syncthreads();
    }
    // recompute pivot with a simple serial scan by thread 0 (128 adds, negligible)
    if (t == 0) {
        // hist[] now holds within-warp inclusive scans; rebuild totals serially from wtot
        int run = 0;
        int tb = -1, m = 0;
        for (int q = 0; q < 128; q++) {
            int wq = q >> 5;
            int base = 0;
            for (int k2 = 0; k2 < wq; k2++) base += wtot[k2];
            int incl = hist[q] + base;
            int excl = run;      // running exclusive
            int h = incl - excl;
            run = incl;
            if (incl >= KNB && excl < KNB && tb < 0) { tb = q; m = excl; }
            (void)h;
        }
        scal[2] = tb; scal[3] = m;
    }
    __syncthreads();
    int tb = scal[2], m = scal[3];
    for (int i = t; i < cnt; i += NT) {
        int bk = min(127, (int)(sd[i] * bsc));
        if (bk < tb) {
            int k = atomicAdd(&scal[1], 1);
            nlist[k] = sid[i];
        } else if (bk == tb) {
            int k = atomicAdd(&scal[4], 1);
            if (k < 256) { td[k] = sd[i]; tdi[k] = sid[i]; }
        }
    }
    __syncthreads();
    int bn = min(scal[4], 256), rem = KNB - m;
    for (int i = t; i < bn; i += NT) {
        float di = td[i]; int ii = tdi[i];
        int rank = 0;
        for (int j2 = 0; j2 < bn; j2++) {
            float dj = td[j2]; int ij = tdi[j2];
            if (dj < di || (dj == di && ij < ii)) rank++;
        }
        if (rank < rem) {
            int k = atomicAdd(&scal[1], 1);
            nlist[k] = tdi[i];
        }
    }
    if (t == 0) { *cnt_out = KNB; g_cnt[cc] = KNB; }
    __syncthreads();
}

__global__ void __launch_bounds__(NT, 2)
k_fuse(const float* __restrict__ x, const float* __restrict__ b0,
       float* __restrict__ octr, float* __restrict__ obat) {
    extern __shared__ float sm[];
    int bid = blockIdx.x, t = threadIdx.x;
    if (bid < BB) { fps_role(sm, bid, t, octr, obat); return; }

    int blk = bid - BB;
    float*    sA    = sm;                          // 128*132 f32 (also nbr scratch)
    uint32_t* sB0   = (uint32_t*)(sm + 128*SROW);
    uint32_t* sB1   = sB0 + 4096;
    float*    bias  = sm + 128*SROW + 8192;        // 128
    int*      nlist = (int*)(bias + 128);          // 128 ints
    int*      cnt2  = nlist + 128;                 // 2 ints
    int w = t >> 5, lane = t & 31;
    if (t < 128) bias[t] = b0[t];
    stageB(sB0, g_WF0, t);

#pragma unroll 1
    for (int half = 0; half < 2; half++) {
        int cc = 2*blk + half;
        int b = cc >> 11, sIdx = cc & 2047;
        if (t == 0) {
            while (*((volatile int*)&g_prog[b]) <= sIdx) __nanosleep(128);
        }
        __syncthreads();
        __threadfence();
        nbr_one(sA, nlist + half*KNB, cnt2 + half, cc, t);
    }
    __syncthreads();

    // gather: 2 threads per row; row e, half h
    int e = t >> 1, h = t & 1;
    int c2 = 2*blk + (e >> 6);
    int cnt_my = cnt2[e >> 6];
    int jn = nlist[e];
    float* row = sA + e*SROW;
    __syncthreads();    // nbr scratch reads complete before overwrite
    float4 z4 = make_float4(0.f, 0.f, 0.f, 0.f);
    if ((e & 63) < cnt_my) {
        int bcl = c2 >> 11;
        const float4* xr = (const float4*)(x + (size_t)(bcl*NPTS + jn)*CIN) + h*8;
#pragma unroll
        for (int q = 0; q < 8; q++)
            *(float4*)(row + h*32 + 4*q) = xr[q];
        if (h == 0) {
            float4 P = g_pos4[bcl*NPTS + jn];
            row[64] = P.x - __ldcg(&g_ctr[c2*3]);
            row[65] = P.y - __ldcg(&g_ctr[c2*3+1]);
            row[66] = P.z - __ldcg(&g_ctr[c2*3+2]);
            row[67] = 0.f;
            *(float4*)(row + 68) = z4;
            *(float4*)(row + 72) = z4;
            *(float4*)(row + 76) = z4;
        }
    } else {
#pragma unroll
        for (int q = 0; q < 8; q++)
            *(float4*)(row + h*32 + 4*q) = z4;
        if (h == 0) {
            *(float4*)(row + 64) = z4;
            *(float4*)(row + 68) = z4;
            *(float4*)(row + 72) = z4;
            *(float4*)(row + 76) = z4;
        }
    }

    float acc[16][4];
#pragma unroll
    for (int i = 0; i < 16; i++)
#pragma unroll
        for (int r = 0; r < 4; r++) acc[i][r] = 0.f;

    uint32_t* bufs[2] = { sB0, sB1 };
#pragma unroll 1
    for (int s = 0; s < 3; s++) {
        CP_WAIT0();
        __syncthreads();
        if (s + 1 < 3) stageB(bufs[(s+1)&1], g_WF0 + (s+1)*4096, t);
        gemm_slab(sA, bufs[s&1], acc, w, lane, s*32, (s < 2) ? 2 : 1);
    }

    epi_to_stage(sA, acc, bias, w, lane);
    __syncthreads();

    stage_to_H(g_H0h + (size_t)blk * 4096, sA, t);

    if (t < 128) {
        int cnt0 = cnt2[0], cnt1 = cnt2[1];
        float ssum = 0.f, ssq = 0.f;
        for (int r = 0; r < 128; r++) {
            bool val = (r & 63) < ((r >> 6) ? cnt1 : cnt0);
            float v = sA[r*SROW + t];
            if (val) { ssum += v; ssq = fmaf(v, v, ssq); }
        }
        atomicAdd(&g_stat[0][0][blk & 31][t], (double)ssum);
        atomicAdd(&g_stat[0][1][blk & 31][t], (double)ssq);
    }
}

// ---------------- bn prepare ----------------
__global__ void k_prep(const float* __restrict__ gamma,
                       const float* __restrict__ beta, int layer) {
    int t = threadIdx.x;
    int local = 0;
    for (int i = t; i < BSZ; i += 128) local += g_cnt[i];
    __shared__ int sred[4];
    int lane = t & 31, w = t >> 5;
#pragma unroll
    for (int off = 16; off > 0; off >>= 1)
        local += __shfl_down_sync(0xffffffffu, local, off);
    if (lane == 0) sred[w] = local;
    __syncthreads();
    double cntd = (double)(sred[0] + sred[1] + sred[2] + sred[3]);
    double s = 0.0, q = 0.0;
    for (int k = 0; k < 32; k++) {
        s += g_stat[layer][0][k][t];
        q += g_stat[layer][1][k][t];
    }
    double mean = s / cntd;
    double var = q / cntd - mean * mean;
    if (var < 0.0) var = 0.0;
    double a = (double)gamma[t] * rsqrt(var + 1e-5);
    g_scale[layer][t] = (float)a;
    g_shift[layer][t] = (float)((double)beta[t] - mean * a);
}

// ---------------- layer 1 (256t, 8 warps) ----------------
__global__ void __launch_bounds__(NT, 2) k_l1(const float* __restrict__ b1) {
    extern __shared__ float sm[];
    float*    sA   = sm;
    uint32_t* sB0  = (uint32_t*)(sm + 128*SROW);
    uint32_t* sB1  = sB0 + 4096;
    float*    bias = sm + 128*SROW + 8192;
    float*    sc   = bias + 128;
    float*    sh   = sc + 128;
    int t = threadIdx.x, w = t >> 5, lane = t & 31, blk = blockIdx.x;
    if (t < 128) { bias[t] = b1[t]; sc[t] = g_scale[0][t]; sh[t] = g_shift[0][t]; }

    stageB(sB0, g_WF1, t);
    __syncthreads();

    H_to_stage(sA, g_H0h + (size_t)blk * 4096, t, sc, sh);

    float acc[16][4];
#pragma unroll
    for (int i = 0; i < 16; i++)
#pragma unroll
        for (int r = 0; r < 4; r++) acc[i][r] = 0.f;

    uint32_t* bufs[2] = { sB0, sB1 };
#pragma unroll 1
    for (int s = 0; s < 4; s++) {
        CP_WAIT0();
        __syncthreads();
        if (s + 1 < 4) stageB(bufs[(s+1)&1], g_WF1 + (s+1)*4096, t);
        gemm_slab(sA, bufs[s&1], acc, w, lane, s*32, 2);
    }

    epi_to_stage(sA, acc, bias, w, lane);
    __syncthreads();

    stage_to_H(g_H1h + (size_t)blk * 4096, sA, t);

    if (t < 128) {
        int cnt0 = g_cnt[blk*2], cnt1 = g_cnt[blk*2+1];
        float ssum = 0.f, ssq = 0.f;
        for (int r = 0; r < 128; r++) {
            bool val = (r & 63) < ((r >> 6) ? cnt1 : cnt0);
            float v = sA[r*SROW + t];
            if (val) { ssum += v; ssq = fmaf(v, v, ssq); }
        }
        atomicAdd(&g_stat[1][0][blk & 31][t], (double)ssum);
        atomicAdd(&g_stat[1][1][blk & 31][t], (double)ssq);
    }
}

// ---------------- layer 2 (256t, 8 warps) ----------------
__global__ void __launch_bounds__(NT, 2) k_l2(const float* __restrict__ b2,
                                              float* __restrict__ outp) {
    extern __shared__ float sm[];
    float*    sA   = sm;
    uint32_t* sB0  = (uint32_t*)(sm + 128*SROW);
    uint32_t* sB1  = sB0 + 4096;
    float*    bias = sm + 128*SROW + 8192;
    float*    sc   = bias + 128;
    float*    sh   = sc + 128;
    int t = threadIdx.x, w = t >> 5, lane = t & 31, blk = blockIdx.x;
    if (t < 128) { bias[t] = b2[t]; sc[t] = g_scale[1][t]; sh[t] = g_shift[1][t]; }

    stageB(sB0, g_WF2, t);
    __syncthreads();

    H_to_stage(sA, g_H1h + (size_t)blk * 4096, t, sc, sh);

    float acc[16][4];
#pragma unroll
    for (int i = 0; i < 16; i++)
#pragma unroll
        for (int r = 0; r < 4; r++) acc[i][r] = 0.f;

    uint32_t* bufs[2] = { sB0, sB1 };
#pragma unroll 1
    for (int s = 0; s < 4; s++) {
        CP_WAIT0();
        __syncthreads();
        if (s + 1 < 4) stageB(bufs[(s+1)&1], g_WF2 + (s+1)*4096, t);
        gemm_slab(sA, bufs[s&1], acc, w, lane, s*32, 2);
    }

    epi_to_stage(sA, acc, bias, w, lane);
    __syncthreads();

    if (t < 128) {
        int cnt0 = g_cnt[blk*2], cnt1 = g_cnt[blk*2+1];
        const float NINF = __int_as_float(0xff800000);
        float m0 = NINF, m1 = NINF;
        for (int r = 0; r < 64; r++)
            if (r < cnt0) m0 = fmaxf(m0, sA[r*SROW + t]);
        for (int r = 64; r < 128; r++)
            if ((r - 64) < cnt1) m1 = fmaxf(m1, sA[r*SROW + t]);
        outp[(size_t)(blk*2)     * HID + t] = m0;
        outp[(size_t)(blk*2 + 1) * HID + t] = m1;
    }
}

// ---------------- launch ----------------
extern "C" void kernel_launch(void* const* d_in, const int* in_sizes, int n_in,
                              void* d_out, int out_size) {
    const float* x   = (const float*)d_in[0];
    const float* pos = (const float*)d_in[1];
    const float* W0  = (const float*)d_in[3];
    const float* b0  = (const float*)d_in[4];
    const float* g0  = (const float*)d_in[5];
    const float* be0 = (const float*)d_in[6];
    const float* W1  = (const float*)d_in[7];
    const float* b1  = (const float*)d_in[8];
    const float* g1  = (const float*)d_in[9];
    const float* be1 = (const float*)d_in[10];
    const float* W2  = (const float*)d_in[11];
    const float* b2  = (const float*)d_in[12];
    float* out = (float*)d_out;

    float* octr = (out_size >= BSZ*HID + BSZ*3) ? out + (size_t)BSZ*HID : nullptr;
    float* obat = (out_size >= BSZ*HID + BSZ*3 + BSZ) ? out + (size_t)BSZ*131 : nullptr;

    int smB = (128*SROW + 8192 + 384 + 132) * 4;   // 102,416 B -> 2 CTAs/SM (16 warps)
    cudaFuncSetAttribute(k_fuse, cudaFuncAttributeMaxDynamicSharedMemorySize, smB);
    cudaFuncSetAttribute(k_l1,  cudaFuncAttributeMaxDynamicSharedMemorySize, smB);
    cudaFuncSetAttribute(k_l2,  cudaFuncAttributeMaxDynamicSharedMemorySize, smB);

    // k_fuse is launch #4 -> ncu capture slot
    k_pA<<<(49160 + 255)/256, 256>>>(pos);
    k_pB<<<(14336 + 255)/256, 256>>>(W0, W1);
    k_pC<<<(8192 + 255)/256, 256>>>(W2);
    k_fuse<<<BB + NBLK, NT, smB>>>(x, b0, octr, obat);
    k_prep<<<1, 128>>>(g0, be0, 0);
    k_l1<<<NBLK, NT, smB>>>(b1);
    k_prep<<<1, 128>>>(g1, be1, 1);
    k_l2<<<NBLK, NT, smB>>>(b2, out);
}